// round 4
// baseline (speedup 1.0000x reference)
#include <cuda_runtime.h>

#define N_NODES 100000
#define E_EDGES 1000000
#define H_DIM   64
#define OUT_DIM 16
#define R_REL   90
#define B_BAS   8
#define SC_EPB  2048

typedef unsigned long long ull;

// ---------------- device scratch ----------------
__device__ float g_W0[R_REL * H_DIM * H_DIM];
__device__ float g_W1[R_REL * H_DIM * H_DIM];
__device__ float g_W2[R_REL * H_DIM * OUT_DIM];
__device__ int   g_cnt[R_REL];
__device__ int   g_off[R_REL + 1];
__device__ int   g_cur[R_REL];
__device__ int4  g_edges[E_EDGES];           // (src, dst, rel, norm bits)
__device__ float g_h1[N_NODES * H_DIM];
__device__ float g_h2[N_NODES * H_DIM];

// ---------------- counting sort by relation ----------------
__global__ void k_zero_cnt() {
    if (threadIdx.x < R_REL) g_cnt[threadIdx.x] = 0;
}

__global__ void __launch_bounds__(256) k_hist(const int* __restrict__ et) {
    __shared__ int h[R_REL];
    int t = threadIdx.x;
    for (int i = t; i < R_REL; i += 256) h[i] = 0;
    __syncthreads();
    int base = blockIdx.x * SC_EPB;
#pragma unroll
    for (int i = 0; i < 8; i++) {
        int e = base + i * 256 + t;
        if (e < E_EDGES) atomicAdd(&h[et[e]], 1);
    }
    __syncthreads();
    for (int i = t; i < R_REL; i += 256)
        if (h[i]) atomicAdd(&g_cnt[i], h[i]);
}

__global__ void k_scan() {
    __shared__ int s[R_REL];
    if (threadIdx.x < R_REL) s[threadIdx.x] = g_cnt[threadIdx.x];
    __syncthreads();
    if (threadIdx.x == 0) {
        int a = 0;
        for (int r = 0; r < R_REL; r++) {
            int c = s[r]; s[r] = a; a += c;
        }
        g_off[R_REL] = a;
    }
    __syncthreads();
    if (threadIdx.x < R_REL) {
        g_off[threadIdx.x] = s[threadIdx.x];
        g_cur[threadIdx.x] = s[threadIdx.x];
    }
}

__global__ void __launch_bounds__(256) k_scatter(const int* __restrict__ src,
                                                 const int* __restrict__ dst,
                                                 const int* __restrict__ et,
                                                 const float* __restrict__ norm) {
    __shared__ int scnt[R_REL];
    __shared__ int sbase[R_REL];
    int t = threadIdx.x;
    for (int i = t; i < R_REL; i += 256) scnt[i] = 0;
    __syncthreads();
    int base = blockIdx.x * SC_EPB;
    int r[8], rk[8];
#pragma unroll
    for (int i = 0; i < 8; i++) {
        int e = base + i * 256 + t;
        if (e < E_EDGES) {
            r[i]  = et[e];
            rk[i] = atomicAdd(&scnt[r[i]], 1);
        } else r[i] = -1;
    }
    __syncthreads();
    for (int i = t; i < R_REL; i += 256)
        sbase[i] = scnt[i] ? atomicAdd(&g_cur[i], scnt[i]) : 0;
    __syncthreads();
#pragma unroll
    for (int i = 0; i < 8; i++) {
        int e = base + i * 256 + t;
        if (r[i] >= 0) {
            int p = sbase[r[i]] + rk[i];
            g_edges[p] = make_int4(src[e], dst[e], r[i], __float_as_int(norm[e]));
        }
    }
}

// ---------------- all W_r in one launch ----------------
#define W64_SZ (R_REL * H_DIM * H_DIM)     // 368640
#define W16_SZ (R_REL * H_DIM * OUT_DIM)   // 92160
__global__ void k_W_all(const float* __restrict__ c0, const float* __restrict__ b0,
                        const float* __restrict__ c1, const float* __restrict__ b1,
                        const float* __restrict__ c2, const float* __restrict__ b2) {
    int idx = blockIdx.x * blockDim.x + threadIdx.x;
    const float* coeff; const float* bases; float* W; int od; int li;
    if (idx < W64_SZ)            { coeff = c0; bases = b0; W = g_W0; od = H_DIM; li = idx; }
    else if (idx < 2 * W64_SZ)   { coeff = c1; bases = b1; W = g_W1; od = H_DIM; li = idx - W64_SZ; }
    else if (idx < 2 * W64_SZ + W16_SZ)
                                 { coeff = c2; bases = b2; W = g_W2; od = OUT_DIM; li = idx - 2 * W64_SZ; }
    else return;
    int r  = li / (H_DIM * od);
    int io = li - r * (H_DIM * od);
    float s = 0.f;
#pragma unroll
    for (int b = 0; b < B_BAS; b++)
        s = fmaf(coeff[r * B_BAS + b], bases[b * H_DIM * od + io], s);
    W[li] = s;
}

// ---------------- fused bias init (h1, h2, out) ----------------
#define H64Q (N_NODES * H_DIM / 4)   // 1.6M float4
#define H16Q (N_NODES * OUT_DIM / 4) // 0.4M float4
__global__ void k_init_all(const float* __restrict__ bias0,
                           const float* __restrict__ bias1,
                           const float* __restrict__ bias2,
                           float* __restrict__ out) {
    int idx = blockIdx.x * blockDim.x + threadIdx.x;
    if (idx < H64Q) {
        ((float4*)g_h1)[idx] = ((const float4*)bias0)[idx & 15];
    } else if (idx < 2 * H64Q) {
        int i = idx - H64Q;
        ((float4*)g_h2)[i] = ((const float4*)bias1)[i & 15];
    } else if (idx < 2 * H64Q + H16Q) {
        int i = idx - 2 * H64Q;
        ((float4*)out)[i] = ((const float4*)bias2)[i & 3];
    }
}

__global__ void k_relu(float* __restrict__ h) {
    int idx = blockIdx.x * blockDim.x + threadIdx.x;
    if (idx < N_NODES * H_DIM / 4) {
        float4 v = ((float4*)h)[idx];
        v.x = fmaxf(v.x, 0.f); v.y = fmaxf(v.y, 0.f);
        v.z = fmaxf(v.z, 0.f); v.w = fmaxf(v.w, 0.f);
        ((float4*)h)[idx] = v;
    }
}

// ---------------- f32x2 helpers ----------------
#define FMA2(acc, a, b) \
    asm("fma.rn.f32x2 %0, %1, %2, %0;" : "+l"(acc) : "l"(a), "l"(b))
#define MUL2(acc, b) \
    asm("mul.rn.f32x2 %0, %0, %1;" : "+l"(acc) : "l"(b))
#define DUP2(d, s) \
    asm("mov.b64 %0, {%1, %1};" : "=l"(d) : "r"(__float_as_uint(s)))
#define UNPK2(f0, f1, s) \
    asm("mov.b64 {%0, %1}, %2;" : "=f"(f0), "=f"(f1) : "l"(s))

// ---------------- edge kernel, H->H ----------------
// 2 threads per edge: lane L owns outs [0,32), lane L+16 owns [32,64).
// Warp covers 16 edges per round, stride 128 over the block's 256 edges.
// Per-thread state: 16 f32x2 accs (32 regs) -> no spills.
// W in two SMEM copies offset 16B so the two half-groups' broadcasts hit
// disjoint banks.
__global__ void __launch_bounds__(256, 2) k_edge64(const float* __restrict__ x,
                                                   const float* __restrict__ W,
                                                   float* __restrict__ h) {
    __shared__ float Ws[H_DIM * 32 + 4 + H_DIM * 32];
    float* WsA = Ws;
    float* WsB = Ws + H_DIM * 32 + 4;

    const int tid  = threadIdx.x;
    const int lane = tid & 31;
    const int warp = tid >> 5;
    const int half = lane >> 4;
    const int pidx = lane & 15;

    int base = blockIdx.x * 256;
    int lim  = min(base + 256, E_EDGES);
    int pos  = base;
    while (pos < lim) {
        int r      = g_edges[pos].z;
        int segEnd = min(lim, g_off[r + 1]);
        {
            const float4* Wg = (const float4*)(W + r * (H_DIM * H_DIM));
#pragma unroll
            for (int k = 0; k < 4; k++) {
                int g   = tid + k * 256;
                int row = g >> 4, o4 = g & 15;
                float4 v = Wg[g];
                float* d = (o4 < 8) ? &WsA[row * 32 + o4 * 4]
                                    : &WsB[row * 32 + (o4 - 8) * 4];
                *(float4*)d = v;
            }
        }
        __syncthreads();
        const float* Wh = half ? WsB : WsA;

#pragma unroll 1
        for (int e = pos + warp * 16 + pidx; e < segEnd; e += 128) {
            int4 ed = g_edges[e];
            const float* xv = x + ed.x * H_DIM;
            ull acc[16];
#pragma unroll
            for (int j = 0; j < 16; j++) acc[j] = 0ull;

#pragma unroll 1
            for (int ic = 0; ic < 8; ic++) {
                float4 a0 = *(const float4*)(xv + ic * 8);
                float4 a1 = *(const float4*)(xv + ic * 8 + 4);
                float xs[8] = {a0.x, a0.y, a0.z, a0.w, a1.x, a1.y, a1.z, a1.w};
#pragma unroll
                for (int i = 0; i < 8; i++) {
                    ull A;
                    DUP2(A, xs[i]);
                    const float* Wrow = Wh + (ic * 8 + i) * 32;
#pragma unroll
                    for (int j = 0; j < 4; j++) {
                        ulonglong2 w = *(const ulonglong2*)(Wrow + j * 8);
                        ulonglong2 w2 = *(const ulonglong2*)(Wrow + j * 8 + 4);
                        FMA2(acc[4 * j],     A, w.x);
                        FMA2(acc[4 * j + 1], A, w.y);
                        FMA2(acc[4 * j + 2], A, w2.x);
                        FMA2(acc[4 * j + 3], A, w2.y);
                    }
                }
            }

            ull NN;
            DUP2(NN, __int_as_float(ed.w));
#pragma unroll
            for (int j = 0; j < 16; j++) MUL2(acc[j], NN);

            float* hp = h + ed.y * H_DIM + half * 32;
#pragma unroll
            for (int q = 0; q < 8; q++) {
                float f0, f1, f2, f3;
                UNPK2(f0, f1, acc[2 * q]);
                UNPK2(f2, f3, acc[2 * q + 1]);
                asm volatile("red.global.add.v4.f32 [%0], {%1, %2, %3, %4};"
                             :: "l"(hp + q * 4), "f"(f0), "f"(f1), "f"(f2), "f"(f3)
                             : "memory");
            }
        }
        __syncthreads();
        pos = segEnd;
    }
}

// ---------------- edge kernel, H->OUT: thread-per-edge, relu fused ----------
__global__ void __launch_bounds__(256, 4) k_edge16(const float* __restrict__ x,
                                                   const float* __restrict__ W,
                                                   float* __restrict__ h) {
    __shared__ float Ws[H_DIM * OUT_DIM];
    int base = blockIdx.x * 256;
    int lim  = min(base + 256, E_EDGES);
    int pos  = base;
    while (pos < lim) {
        int r      = g_edges[pos].z;
        int segEnd = min(lim, g_off[r + 1]);
        ((float4*)Ws)[threadIdx.x] =
            ((const float4*)(W + r * (H_DIM * OUT_DIM)))[threadIdx.x];
        __syncthreads();

        int e = pos + threadIdx.x;
        if (e < segEnd) {
            int4  ed  = g_edges[e];
            const float* xv = x + ed.x * H_DIM;
            ull acc[8];
#pragma unroll
            for (int j = 0; j < 8; j++) acc[j] = 0ull;

#pragma unroll
            for (int ic = 0; ic < 8; ic++) {
                float4 a0 = *(const float4*)(xv + ic * 8);
                float4 a1 = *(const float4*)(xv + ic * 8 + 4);
                float xs[8] = {a0.x, a0.y, a0.z, a0.w, a1.x, a1.y, a1.z, a1.w};
#pragma unroll
                for (int i = 0; i < 8; i++) {
                    ull A;
                    DUP2(A, fmaxf(xs[i], 0.f));     // relu fused (prev layer)
                    const float* Wrow = Ws + (ic * 8 + i) * OUT_DIM;
#pragma unroll
                    for (int j = 0; j < 4; j++) {
                        ulonglong2 w = *(const ulonglong2*)(Wrow + j * 4);
                        FMA2(acc[2 * j],     A, w.x);
                        FMA2(acc[2 * j + 1], A, w.y);
                    }
                }
            }
            ull NN;
            DUP2(NN, __int_as_float(ed.w));
#pragma unroll
            for (int j = 0; j < 8; j++) MUL2(acc[j], NN);

            float* hp = h + ed.y * OUT_DIM;
#pragma unroll
            for (int q = 0; q < 4; q++) {
                float f0, f1, f2, f3;
                UNPK2(f0, f1, acc[2 * q]);
                UNPK2(f2, f3, acc[2 * q + 1]);
                asm volatile("red.global.add.v4.f32 [%0], {%1, %2, %3, %4};"
                             :: "l"(hp + q * 4), "f"(f0), "f"(f1), "f"(f2), "f"(f3)
                             : "memory");
            }
        }
        __syncthreads();
        pos = segEnd;
    }
}

// ---------------- launch ----------------
extern "C" void kernel_launch(void* const* d_in, const int* in_sizes, int n_in,
                              void* d_out, int out_size) {
    const float* feats  = (const float*)d_in[0];
    const float* coeff0 = (const float*)d_in[1];
    const float* bases0 = (const float*)d_in[2];
    const float* bias0  = (const float*)d_in[3];
    const float* coeff1 = (const float*)d_in[4];
    const float* bases1 = (const float*)d_in[5];
    const float* bias1  = (const float*)d_in[6];
    const float* coeff2 = (const float*)d_in[7];
    const float* bases2 = (const float*)d_in[8];
    const float* bias2  = (const float*)d_in[9];
    const int*   src    = (const int*)d_in[10];
    const int*   dst    = (const int*)d_in[11];
    const int*   etype  = (const int*)d_in[12];
    const float* norm   = (const float*)d_in[13];
    float*       out    = (float*)d_out;

    const int SB = (E_EDGES + SC_EPB - 1) / SC_EPB;
    const int EB = (E_EDGES + 255) / 256;

    k_zero_cnt<<<1, 128>>>();
    k_hist<<<SB, 256>>>(etype);
    k_scan<<<1, 128>>>();
    k_scatter<<<SB, 256>>>(src, dst, etype, norm);

    k_W_all<<<(2 * W64_SZ + W16_SZ + 255) / 256, 256>>>(coeff0, bases0,
                                                        coeff1, bases1,
                                                        coeff2, bases2);
    k_init_all<<<(2 * H64Q + H16Q + 255) / 256, 256>>>(bias0, bias1, bias2, out);

    float *h1, *h2, *W0, *W1, *W2;
    cudaGetSymbolAddress((void**)&h1, g_h1);
    cudaGetSymbolAddress((void**)&h2, g_h2);
    cudaGetSymbolAddress((void**)&W0, g_W0);
    cudaGetSymbolAddress((void**)&W1, g_W1);
    cudaGetSymbolAddress((void**)&W2, g_W2);

    // layer 0: feats -> h1
    k_edge64<<<EB, 256>>>(feats, W0, h1);
    k_relu<<<(N_NODES * H_DIM / 4 + 255) / 256, 256>>>(h1);

    // layer 1: relu'd h1 -> h2
    k_edge64<<<EB, 256>>>(h1, W1, h2);

    // layer 2: relu fused in gather: h2 -> out
    k_edge16<<<EB, 256>>>(h2, W2, out);
}

// round 5
// speedup vs baseline: 1.2152x; 1.2152x over previous
#include <cuda_runtime.h>

#define N_NODES 100000
#define E_EDGES 1000000
#define H_DIM   64
#define OUT_DIM 16
#define R_REL   90
#define B_BAS   8
#define SC_EPB  2048
#define SB_BLKS ((E_EDGES + SC_EPB - 1) / SC_EPB)   // 489

typedef unsigned long long ull;

// ---------------- device scratch ----------------
__device__ float g_W0[R_REL * H_DIM * H_DIM];
__device__ float g_W1[R_REL * H_DIM * H_DIM];
__device__ float g_W2[R_REL * H_DIM * OUT_DIM];
__device__ int   g_bh[SB_BLKS * R_REL];      // per-block histograms
__device__ int   g_off[R_REL + 1];
__device__ int   g_cur[R_REL];
__device__ int4  g_edges[E_EDGES];           // (src, dst, rel, norm bits)
__device__ float g_h1[N_NODES * H_DIM];
__device__ float g_h2[N_NODES * H_DIM];

#define W64_SZ (R_REL * H_DIM * H_DIM)       // 368640
#define W16_SZ (R_REL * H_DIM * OUT_DIM)     // 92160
#define W_TOT  (2 * W64_SZ + W16_SZ)         // 829440
#define H64Q   (N_NODES * H_DIM / 4)         // 1.6M float4
#define H16Q   (N_NODES * OUT_DIM / 4)       // 0.4M float4
#define FLAT_TOT (2 * H64Q + H16Q + W_TOT)

// ---------------- fused prep: block-hist + W precompute + bias init --------
__global__ void __launch_bounds__(256) k_prep(
    const int* __restrict__ et,
    const float* __restrict__ c0, const float* __restrict__ b0,
    const float* __restrict__ c1, const float* __restrict__ b1,
    const float* __restrict__ c2, const float* __restrict__ b2,
    const float* __restrict__ bias0, const float* __restrict__ bias1,
    const float* __restrict__ bias2, float* __restrict__ out)
{
    int b = blockIdx.x;
    int t = threadIdx.x;
    if (b < SB_BLKS) {
        // per-block histogram, plain store (no global zeroing needed)
        __shared__ int h[R_REL];
        for (int i = t; i < R_REL; i += 256) h[i] = 0;
        __syncthreads();
        int base = b * SC_EPB;
#pragma unroll
        for (int i = 0; i < 8; i++) {
            int e = base + i * 256 + t;
            if (e < E_EDGES) atomicAdd(&h[et[e]], 1);
        }
        __syncthreads();
        for (int i = t; i < R_REL; i += 256)
            g_bh[b * R_REL + i] = h[i];
        return;
    }
    int idx = (b - SB_BLKS) * 256 + t;
    if (idx < H64Q) {
        ((float4*)g_h1)[idx] = ((const float4*)bias0)[idx & 15];
    } else if (idx < 2 * H64Q) {
        int i = idx - H64Q;
        ((float4*)g_h2)[i] = ((const float4*)bias1)[i & 15];
    } else if (idx < 2 * H64Q + H16Q) {
        int i = idx - 2 * H64Q;
        ((float4*)out)[i] = ((const float4*)bias2)[i & 3];
    } else if (idx < FLAT_TOT) {
        int li = idx - (2 * H64Q + H16Q);
        const float* coeff; const float* bases; float* W; int od;
        if (li < W64_SZ)          { coeff = c0; bases = b0; W = g_W0; od = H_DIM; }
        else if (li < 2 * W64_SZ) { coeff = c1; bases = b1; W = g_W1; od = H_DIM; li -= W64_SZ; }
        else                      { coeff = c2; bases = b2; W = g_W2; od = OUT_DIM; li -= 2 * W64_SZ; }
        int r  = li / (H_DIM * od);
        int io = li - r * (H_DIM * od);
        float s = 0.f;
#pragma unroll
        for (int bb = 0; bb < B_BAS; bb++)
            s = fmaf(coeff[r * B_BAS + bb], bases[bb * H_DIM * od + io], s);
        W[li] = s;
    }
}

// ---------------- scan: totals over block-hists, prefix, seed g_cur --------
__global__ void k_scan2() {
    __shared__ int tot[R_REL];
    int t = threadIdx.x;
    if (t < R_REL) {
        int s = 0;
        for (int b = 0; b < SB_BLKS; b++) s += g_bh[b * R_REL + t];
        tot[t] = s;
    }
    __syncthreads();
    if (t == 0) {
        int a = 0;
        for (int r = 0; r < R_REL; r++) {
            int c = tot[r]; tot[r] = a; a += c;
        }
        g_off[R_REL] = a;
    }
    __syncthreads();
    if (t < R_REL) {
        g_off[t] = tot[t];
        g_cur[t] = tot[t];
    }
}

__global__ void __launch_bounds__(256) k_scatter(const int* __restrict__ src,
                                                 const int* __restrict__ dst,
                                                 const int* __restrict__ et,
                                                 const float* __restrict__ norm) {
    __shared__ int scnt[R_REL];
    __shared__ int sbase[R_REL];
    int t = threadIdx.x;
    for (int i = t; i < R_REL; i += 256) scnt[i] = 0;
    __syncthreads();
    int base = blockIdx.x * SC_EPB;
    int r[8], rk[8];
#pragma unroll
    for (int i = 0; i < 8; i++) {
        int e = base + i * 256 + t;
        if (e < E_EDGES) {
            r[i]  = et[e];
            rk[i] = atomicAdd(&scnt[r[i]], 1);
        } else r[i] = -1;
    }
    __syncthreads();
    for (int i = t; i < R_REL; i += 256)
        sbase[i] = scnt[i] ? atomicAdd(&g_cur[i], scnt[i]) : 0;
    __syncthreads();
#pragma unroll
    for (int i = 0; i < 8; i++) {
        int e = base + i * 256 + t;
        if (r[i] >= 0) {
            int p = sbase[r[i]] + rk[i];
            g_edges[p] = make_int4(src[e], dst[e], r[i], __float_as_int(norm[e]));
        }
    }
}

__global__ void k_relu(float* __restrict__ h) {
    int idx = blockIdx.x * blockDim.x + threadIdx.x;
    if (idx < N_NODES * H_DIM / 4) {
        float4 v = ((float4*)h)[idx];
        v.x = fmaxf(v.x, 0.f); v.y = fmaxf(v.y, 0.f);
        v.z = fmaxf(v.z, 0.f); v.w = fmaxf(v.w, 0.f);
        ((float4*)h)[idx] = v;
    }
}

// ---------------- f32x2 helpers ----------------
#define FMA2(acc, a, b) \
    asm("fma.rn.f32x2 %0, %1, %2, %0;" : "+l"(acc) : "l"(a), "l"(b))
#define MUL2(acc, b) \
    asm("mul.rn.f32x2 %0, %0, %1;" : "+l"(acc) : "l"(b))
#define DUP2(d, s) \
    asm("mov.b64 %0, {%1, %1};" : "=l"(d) : "r"(__float_as_uint(s)))
#define UNPK2(f0, f1, s) \
    asm("mov.b64 {%0, %1}, %2;" : "=f"(f0), "=f"(f1) : "l"(s))

// ---------------- edge kernel, H->H (R3 layout: 2 edges x 32 outs/thread) --
__global__ void __launch_bounds__(256, 2) k_edge64(const float* __restrict__ x,
                                                   const float* __restrict__ W,
                                                   float* __restrict__ h) {
    __shared__ float Ws[H_DIM * 32 + 4 + H_DIM * 32];   // A | pad | B
    float* WsA = Ws;
    float* WsB = Ws + H_DIM * 32 + 4;

    const int tid  = threadIdx.x;
    const int lane = tid & 31;
    const int warp = tid >> 5;
    const int half = lane >> 4;
    const int pidx = lane & 15;

    int base = blockIdx.x * 256;
    int lim  = min(base + 256, E_EDGES);
    int pos  = base;
    while (pos < lim) {
        int r      = g_edges[pos].z;
        int segEnd = min(lim, g_off[r + 1]);
        {
            const float4* Wg = (const float4*)(W + r * (H_DIM * H_DIM));
#pragma unroll
            for (int k = 0; k < 4; k++) {
                int g   = tid + k * 256;
                int row = g >> 4, o4 = g & 15;
                float4 v = Wg[g];
                float* d = (o4 < 8) ? &WsA[row * 32 + o4 * 4]
                                    : &WsB[row * 32 + (o4 - 8) * 4];
                *(float4*)d = v;
            }
        }
        __syncthreads();

        int e0 = pos + warp * 32 + 2 * pidx;
        int e1 = e0 + 1;
        if (e0 < segEnd) {
            bool v1  = (e1 < segEnd);
            int4 ed0 = g_edges[e0];
            int4 ed1 = v1 ? g_edges[e1] : ed0;
            const float* x0 = x + ed0.x * H_DIM;
            const float* x1 = x + ed1.x * H_DIM;
            const float* Wh = half ? WsB : WsA;

            ull acc[32];
#pragma unroll
            for (int j = 0; j < 32; j++) acc[j] = 0ull;

            for (int ic = 0; ic < 8; ic++) {          // not unrolled (I$)
                float4 a0 = *(const float4*)(x0 + ic * 8);
                float4 a1 = *(const float4*)(x0 + ic * 8 + 4);
                float4 b0 = *(const float4*)(x1 + ic * 8);
                float4 b1 = *(const float4*)(x1 + ic * 8 + 4);
                float xs0[8] = {a0.x, a0.y, a0.z, a0.w, a1.x, a1.y, a1.z, a1.w};
                float xs1[8] = {b0.x, b0.y, b0.z, b0.w, b1.x, b1.y, b1.z, b1.w};
#pragma unroll
                for (int i = 0; i < 8; i++) {
                    ull A0, A1;
                    DUP2(A0, xs0[i]);
                    DUP2(A1, xs1[i]);
                    const float* Wrow = Wh + (ic * 8 + i) * 32;
#pragma unroll
                    for (int j = 0; j < 8; j++) {
                        ulonglong2 w = *(const ulonglong2*)(Wrow + j * 4);
                        FMA2(acc[2 * j],          A0, w.x);
                        FMA2(acc[2 * j + 1],      A0, w.y);
                        FMA2(acc[16 + 2 * j],     A1, w.x);
                        FMA2(acc[16 + 2 * j + 1], A1, w.y);
                    }
                }
            }

            float n0 = __int_as_float(ed0.w);
            float n1 = v1 ? __int_as_float(ed1.w) : 0.f;
            ull NN0, NN1;
            DUP2(NN0, n0);
            DUP2(NN1, n1);
#pragma unroll
            for (int j = 0; j < 16; j++) MUL2(acc[j], NN0);
#pragma unroll
            for (int j = 16; j < 32; j++) MUL2(acc[j], NN1);

            float* hp0 = h + ed0.y * H_DIM + half * 32;
#pragma unroll
            for (int q = 0; q < 8; q++) {
                float f0, f1, f2, f3;
                UNPK2(f0, f1, acc[2 * q]);
                UNPK2(f2, f3, acc[2 * q + 1]);
                asm volatile("red.global.add.v4.f32 [%0], {%1, %2, %3, %4};"
                             :: "l"(hp0 + q * 4), "f"(f0), "f"(f1), "f"(f2), "f"(f3)
                             : "memory");
            }
            if (v1) {
                float* hp1 = h + ed1.y * H_DIM + half * 32;
#pragma unroll
                for (int q = 0; q < 8; q++) {
                    float f0, f1, f2, f3;
                    UNPK2(f0, f1, acc[16 + 2 * q]);
                    UNPK2(f2, f3, acc[16 + 2 * q + 1]);
                    asm volatile("red.global.add.v4.f32 [%0], {%1, %2, %3, %4};"
                                 :: "l"(hp1 + q * 4), "f"(f0), "f"(f1), "f"(f2), "f"(f3)
                                 : "memory");
                }
            }
        }
        __syncthreads();
        pos = segEnd;
    }
}

// ---------------- edge kernel, H->OUT: thread-per-edge, relu fused ----------
__global__ void __launch_bounds__(256, 4) k_edge16(const float* __restrict__ x,
                                                   const float* __restrict__ W,
                                                   float* __restrict__ h) {
    __shared__ float Ws[H_DIM * OUT_DIM];
    int base = blockIdx.x * 256;
    int lim  = min(base + 256, E_EDGES);
    int pos  = base;
    while (pos < lim) {
        int r      = g_edges[pos].z;
        int segEnd = min(lim, g_off[r + 1]);
        ((float4*)Ws)[threadIdx.x] =
            ((const float4*)(W + r * (H_DIM * OUT_DIM)))[threadIdx.x];
        __syncthreads();

        int e = pos + threadIdx.x;
        if (e < segEnd) {
            int4  ed  = g_edges[e];
            const float* xv = x + ed.x * H_DIM;
            ull acc[8];
#pragma unroll
            for (int j = 0; j < 8; j++) acc[j] = 0ull;

#pragma unroll
            for (int ic = 0; ic < 8; ic++) {
                float4 a0 = *(const float4*)(xv + ic * 8);
                float4 a1 = *(const float4*)(xv + ic * 8 + 4);
                float xs[8] = {a0.x, a0.y, a0.z, a0.w, a1.x, a1.y, a1.z, a1.w};
#pragma unroll
                for (int i = 0; i < 8; i++) {
                    ull A;
                    DUP2(A, fmaxf(xs[i], 0.f));     // relu fused (prev layer)
                    const float* Wrow = Ws + (ic * 8 + i) * OUT_DIM;
#pragma unroll
                    for (int j = 0; j < 4; j++) {
                        ulonglong2 w = *(const ulonglong2*)(Wrow + j * 4);
                        FMA2(acc[2 * j],     A, w.x);
                        FMA2(acc[2 * j + 1], A, w.y);
                    }
                }
            }
            ull NN;
            DUP2(NN, __int_as_float(ed.w));
#pragma unroll
            for (int j = 0; j < 8; j++) MUL2(acc[j], NN);

            float* hp = h + ed.y * OUT_DIM;
#pragma unroll
            for (int q = 0; q < 4; q++) {
                float f0, f1, f2, f3;
                UNPK2(f0, f1, acc[2 * q]);
                UNPK2(f2, f3, acc[2 * q + 1]);
                asm volatile("red.global.add.v4.f32 [%0], {%1, %2, %3, %4};"
                             :: "l"(hp + q * 4), "f"(f0), "f"(f1), "f"(f2), "f"(f3)
                             : "memory");
            }
        }
        __syncthreads();
        pos = segEnd;
    }
}

// ---------------- launch ----------------
extern "C" void kernel_launch(void* const* d_in, const int* in_sizes, int n_in,
                              void* d_out, int out_size) {
    const float* feats  = (const float*)d_in[0];
    const float* coeff0 = (const float*)d_in[1];
    const float* bases0 = (const float*)d_in[2];
    const float* bias0  = (const float*)d_in[3];
    const float* coeff1 = (const float*)d_in[4];
    const float* bases1 = (const float*)d_in[5];
    const float* bias1  = (const float*)d_in[6];
    const float* coeff2 = (const float*)d_in[7];
    const float* bases2 = (const float*)d_in[8];
    const float* bias2  = (const float*)d_in[9];
    const int*   src    = (const int*)d_in[10];
    const int*   dst    = (const int*)d_in[11];
    const int*   etype  = (const int*)d_in[12];
    const float* norm   = (const float*)d_in[13];
    float*       out    = (float*)d_out;

    const int EB = (E_EDGES + 255) / 256;
    const int PREP_BLKS = SB_BLKS + (FLAT_TOT + 255) / 256;

    float *h1, *h2, *W0, *W1, *W2;
    cudaGetSymbolAddress((void**)&h1, g_h1);
    cudaGetSymbolAddress((void**)&h2, g_h2);
    cudaGetSymbolAddress((void**)&W0, g_W0);
    cudaGetSymbolAddress((void**)&W1, g_W1);
    cudaGetSymbolAddress((void**)&W2, g_W2);

    // 1: fused prep (hist-store + W precompute + bias inits)
    k_prep<<<PREP_BLKS, 256>>>(etype, coeff0, bases0, coeff1, bases1,
                               coeff2, bases2, bias0, bias1, bias2, out);
    // 2: scan
    k_scan2<<<1, 128>>>();
    // 3: scatter (counting sort by relation)
    k_scatter<<<SB_BLKS, 256>>>(src, dst, etype, norm);
    // 4: layer 0 edges (profiled by ncu window)
    k_edge64<<<EB, 256>>>(feats, W0, h1);
    // 5: relu
    k_relu<<<(N_NODES * H_DIM / 4 + 255) / 256, 256>>>(h1);
    // 6: layer 1 edges
    k_edge64<<<EB, 256>>>(h1, W1, h2);
    // 7: layer 2 edges (relu fused in gather)
    k_edge16<<<EB, 256>>>(h2, W2, out);
}